// round 13
// baseline (speedup 1.0000x reference)
#include <cuda_runtime.h>
#include <cuda_bf16.h>
#include <math.h>
#include <stdint.h>

#define BB 4
#define SS 4096
#define DD 256
#define HH 4
#define HD 64
#define NN (BB*SS)
#define LN_EPS 1e-5f

typedef unsigned short ushortt;

// Scratch (allocation-free). bf16 hi/lo pairs for all GEMM/attention operands.
__device__ ushortt g_xnh[NN*DD], g_xnl[NN*DD];
__device__ ushortt g_qh[NN*DD],  g_ql[NN*DD];
__device__ ushortt g_kh[NN*DD],  g_kl[NN*DD];
__device__ ushortt g_vh[NN*DD],  g_vl[NN*DD];
__device__ ushortt g_hh[NN*DD],  g_hl[NN*DD];
__device__ ushortt g_a1h[NN*DD], g_a1l[NN*DD];
__device__ float   g_att[NN*DD], g_xt[NN*DD];

__device__ __forceinline__ uint32_t smem_u32(const void* p) {
    uint32_t a;
    asm("{ .reg .u64 t; cvta.to.shared.u64 t, %1; cvt.u32.u64 %0, t; }" : "=r"(a) : "l"(p));
    return a;
}
__device__ __forceinline__ void cp_async16(uint32_t saddr, const void* g) {
    asm volatile("cp.async.cg.shared.global [%0], [%1], 16;" :: "r"(saddr), "l"(g));
}
#define CP_COMMIT() asm volatile("cp.async.commit_group;" ::: "memory")
#define CP_WAIT0()  asm volatile("cp.async.wait_group 0;" ::: "memory")

// ---- mma.sync / ldmatrix (base sm_80 ISA) ----
__device__ __forceinline__ void ldmx4(uint32_t* r, uint32_t a) {
    asm volatile("ldmatrix.sync.aligned.m8n8.x4.shared.b16 {%0,%1,%2,%3}, [%4];"
        : "=r"(r[0]), "=r"(r[1]), "=r"(r[2]), "=r"(r[3]) : "r"(a));
}
__device__ __forceinline__ void ldmx4t(uint32_t* r, uint32_t a) {
    asm volatile("ldmatrix.sync.aligned.m8n8.x4.trans.shared.b16 {%0,%1,%2,%3}, [%4];"
        : "=r"(r[0]), "=r"(r[1]), "=r"(r[2]), "=r"(r[3]) : "r"(a));
}
__device__ __forceinline__ void mma_bf16(float* c, const uint32_t* a, const uint32_t* b) {
    asm volatile("mma.sync.aligned.m16n8k16.row.col.f32.bf16.bf16.f32 "
        "{%0,%1,%2,%3}, {%4,%5,%6,%7}, {%8,%9}, {%0,%1,%2,%3};"
        : "+f"(c[0]), "+f"(c[1]), "+f"(c[2]), "+f"(c[3])
        : "r"(a[0]), "r"(a[1]), "r"(a[2]), "r"(a[3]), "r"(b[0]), "r"(b[1]));
}

// hi/lo bf16 split of an fp32 pair (packed bf16x2: e0 in low half).
__device__ __forceinline__ void split2(float e0, float e1, uint32_t& h, uint32_t& l) {
    __nv_bfloat162 hb = __floats2bfloat162_rn(e0, e1);
    h = reinterpret_cast<uint32_t&>(hb);
    float f0 = __bfloat162float(hb.x);
    float f1 = __bfloat162float(hb.y);
    __nv_bfloat162 lb = __floats2bfloat162_rn(e0 - f0, e1 - f1);
    l = reinterpret_cast<uint32_t&>(lb);
}

__device__ __forceinline__ float warp_sum(float v) {
    #pragma unroll
    for (int o = 16; o; o >>= 1) v += __shfl_xor_sync(0xffffffffu, v, o);
    return v;
}

// LayerNorm (optional fused residual) emitting bf16 hi/lo. One block/row, 256 thr.
__global__ void ln_split(const float* __restrict__ x, const float* __restrict__ res,
                         const float* __restrict__ g, const float* __restrict__ b,
                         float* __restrict__ xt_out,
                         ushortt* __restrict__ yh, ushortt* __restrict__ yl) {
    int row = blockIdx.x;
    int t = threadIdx.x;
    size_t i = (size_t)row * DD + t;
    float v = x[i];
    if (res) v += res[i];
    if (xt_out) xt_out[i] = v;

    __shared__ float red1[8], red2[8];
    float s1 = warp_sum(v);
    float s2 = warp_sum(v * v);
    if ((t & 31) == 0) { red1[t >> 5] = s1; red2[t >> 5] = s2; }
    __syncthreads();
    float tot = 0.f, tot2 = 0.f;
    #pragma unroll
    for (int w = 0; w < 8; w++) { tot += red1[w]; tot2 += red2[w]; }
    float mu = tot * (1.f / DD);
    float var = tot2 * (1.f / DD) - mu * mu;
    float rstd = rsqrtf(var + LN_EPS);
    float f = (v - mu) * rstd * g[t] + b[t];
    __nv_bfloat16 hb = __float2bfloat16_rn(f);
    float fh = __bfloat162float(hb);
    __nv_bfloat16 lb = __float2bfloat16_rn(f - fh);
    yh[i] = __bfloat16_as_ushort(hb);
    yl[i] = __bfloat16_as_ushort(lb);
}

// ---------------------------------------------------------------------------
// NT GEMM via mma.sync bf16 hi/lo. A pre-split (cp.async, double-buffered
// 64-wide K-chunks); W fp32 split in-kernel (reg-prefetch). CTA 128x128,
// 8 warps 4(M)x2(N), warp tile 32x64.
// epi: 0 -> write (ch,cl) hi/lo; 1 -> +bias,relu -> (ch,cl); 2 -> +bias+res -> Cf.
#define GRS 72
#define GTIL 9216                      // shorts per 128x72 tile
#define GA(buf)  ((buf) * 2 * GTIL)    // AH at GA, AL at GA+GTIL
#define GW       (4 * GTIL)            // WH, then WL at GW+GTIL
#define SMEM_GEMM (6 * GTIL * 2)       // 110592 B
__global__ void __launch_bounds__(256) gemm_tc(
        const ushortt* __restrict__ ah, const ushortt* __restrict__ al,
        const float* __restrict__ W, const float* __restrict__ bias,
        const float* __restrict__ res, float* __restrict__ Cf,
        ushortt* __restrict__ ch, ushortt* __restrict__ cl, int epi) {
    extern __shared__ ushortt gsm[];
    uint32_t base = smem_u32(gsm);

    int tid = threadIdx.x;
    int w = tid >> 5, lane = tid & 31;
    int lr = lane & 7, grp = lane >> 3;
    int wm = w >> 1, wn = w & 1;
    int bm = blockIdx.y * 128, bn = blockIdx.x * 128;

    int a_row = ((grp & 1) ? 8 : 0) + lr;
    int a_cof = (grp & 2) ? 8 : 0;
    int b_row = ((grp & 2) ? 8 : 0) + lr;
    int b_cof = (grp & 1) ? 8 : 0;

    // A staging map: u = tid + it*256 (it<8): arr = u>>10, rr = (u&1023)>>3, d8 = u&7
    // W staging map: l = tid + it*256 (it<8): rr = l>>4, d4 = (l&15)*4
    float cacc[2][8][4];
    #pragma unroll
    for (int am = 0; am < 2; am++)
        #pragma unroll
        for (int nb = 0; nb < 8; nb++)
            #pragma unroll
            for (int e = 0; e < 4; e++) cacc[am][nb][e] = 0.f;

    // issue A chunk 0 into buf 0
    #pragma unroll
    for (int it = 0; it < 8; it++) {
        int u = tid + it * 256;
        int arr = u >> 10, rem = u & 1023;
        int rr = rem >> 3, d8 = rem & 7;
        const ushortt* src = arr ? al : ah;
        cp_async16(base + (GA(0) + arr * GTIL + rr * GRS + d8 * 8) * 2,
                   &src[(size_t)(bm + rr) * DD + d8 * 8]);
    }
    CP_COMMIT();
    float4 pw[8];
    #pragma unroll
    for (int it = 0; it < 8; it++) {
        int l = tid + it * 256;
        int rr = l >> 4, d4 = (l & 15) * 4;
        pw[it] = *(const float4*)&W[(size_t)(bn + rr) * DD + d4];
    }

    for (int c = 0; c < 4; c++) {
        int buf = c & 1;
        CP_WAIT0();
        // store W chunk c (from regs) as hi/lo
        #pragma unroll
        for (int it = 0; it < 8; it++) {
            int l = tid + it * 256;
            int rr = l >> 4, d4 = (l & 15) * 4;
            uint32_t h01, l01, h23, l23;
            split2(pw[it].x, pw[it].y, h01, l01);
            split2(pw[it].z, pw[it].w, h23, l23);
            *(uint2*)&gsm[GW + rr * GRS + d4]        = make_uint2(h01, h23);
            *(uint2*)&gsm[GW + GTIL + rr * GRS + d4] = make_uint2(l01, l23);
        }
        __syncthreads();

        if (c < 3) {
            #pragma unroll
            for (int it = 0; it < 8; it++) {
                int u = tid + it * 256;
                int arr = u >> 10, rem = u & 1023;
                int rr = rem >> 3, d8 = rem & 7;
                const ushortt* src = arr ? al : ah;
                cp_async16(base + (GA(buf ^ 1) + arr * GTIL + rr * GRS + d8 * 8) * 2,
                           &src[(size_t)(bm + rr) * DD + (c + 1) * 64 + d8 * 8]);
            }
            CP_COMMIT();
            #pragma unroll
            for (int it = 0; it < 8; it++) {
                int l = tid + it * 256;
                int rr = l >> 4, d4 = (l & 15) * 4;
                pw[it] = *(const float4*)&W[(size_t)(bn + rr) * DD + (c + 1) * 64 + d4];
            }
        }

        uint32_t aBase = base + GA(buf) * 2;
        #pragma unroll
        for (int kc = 0; kc < 4; kc++) {
            uint32_t Ah[2][4], Al[2][4];
            #pragma unroll
            for (int am = 0; am < 2; am++) {
                uint32_t aoff = ((wm * 32 + am * 16 + a_row) * GRS + kc * 16 + a_cof) * 2;
                ldmx4(Ah[am], aBase + aoff);
                ldmx4(Al[am], aBase + GTIL * 2 + aoff);
            }
            #pragma unroll
            for (int np = 0; np < 4; np++) {
                uint32_t Bh[4], Bl[4];
                uint32_t boff = ((wn * 64 + np * 16 + b_row) * GRS + kc * 16 + b_cof) * 2;
                ldmx4(Bh, base + GW * 2 + boff);
                ldmx4(Bl, base + (GW + GTIL) * 2 + boff);
                #pragma unroll
                for (int am = 0; am < 2; am++) {
                    mma_bf16(cacc[am][2 * np],     Ah[am], Bh);
                    mma_bf16(cacc[am][2 * np + 1], Ah[am], Bh + 2);
                    mma_bf16(cacc[am][2 * np],     Ah[am], Bl);
                    mma_bf16(cacc[am][2 * np + 1], Ah[am], Bl + 2);
                    mma_bf16(cacc[am][2 * np],     Al[am], Bh);
                    mma_bf16(cacc[am][2 * np + 1], Al[am], Bh + 2);
                }
            }
        }
        __syncthreads();
    }

    // Epilogue from C-fragment layout.
    int cb = (lane & 3) * 2;
    #pragma unroll
    for (int am = 0; am < 2; am++) {
        int r0 = bm + wm * 32 + am * 16 + (lane >> 2);
        #pragma unroll
        for (int nb = 0; nb < 8; nb++) {
            int col = bn + wn * 64 + nb * 8 + cb;
            #pragma unroll
            for (int half = 0; half < 2; half++) {
                int r = r0 + half * 8;
                float v0 = cacc[am][nb][2 * half];
                float v1 = cacc[am][nb][2 * half + 1];
                if (epi >= 1) { v0 += bias[col]; v1 += bias[col + 1]; }
                if (epi == 1) { v0 = fmaxf(v0, 0.f); v1 = fmaxf(v1, 0.f); }
                if (epi == 2) {
                    float2 rv = *(const float2*)&res[(size_t)r * DD + col];
                    *(float2*)&Cf[(size_t)r * DD + col] = make_float2(v0 + rv.x, v1 + rv.y);
                } else {
                    uint32_t hh, ll;
                    split2(v0, v1, hh, ll);
                    *(uint32_t*)&ch[(size_t)r * DD + col] = hh;
                    *(uint32_t*)&cl[(size_t)r * DD + col] = ll;
                }
            }
        }
    }
}

// ---------------------------------------------------------------------------
// Flash attention, mma.sync bf16 hi/lo, inputs pre-split; cp.async staging,
// K/V double-buffered. 128-row q-tile, 128-col kv-tiles, 8 warps.
#define RS 72
#define ATL 9216                       // shorts per 128x72 tile
#define T_Q 0                          // QH, QL at +ATL
#define T_KV 18432                     // per-buf block of 4 tiles (KH,KL,VH,VL)
#define KVBLK (4 * ATL)
#define SMEM_ATTN ((2 * ATL + 2 * KVBLK) * 2)   // 184320 B
__global__ void __launch_bounds__(256, 1) attn_kernel(
        const ushortt* __restrict__ qh, const ushortt* __restrict__ ql,
        const ushortt* __restrict__ kh, const ushortt* __restrict__ kl,
        const ushortt* __restrict__ vh, const ushortt* __restrict__ vl,
        float* __restrict__ att) {
    extern __shared__ ushortt sm16[];
    uint32_t base = smem_u32(sm16);

    int bh = blockIdx.y;
    int b = bh >> 2, h = bh & 3;
    int qt = 31 - blockIdx.x;           // longest first
    int tid = threadIdx.x;
    int w = tid >> 5, lane = tid & 31;
    int lr = lane & 7, grp = lane >> 3;
    int m0 = w * 16;

    size_t rowbase = (size_t)b * SS;
    int colq = h * HD;

    // issue Q (hi/lo) + KV tile 0 as one group
    #pragma unroll
    for (int it = 0; it < 8; it++) {
        int u = tid + it * 256;
        int arr = u >> 10, rem = u & 1023;
        int rr = rem >> 3, d8 = rem & 7;
        const ushortt* src = arr ? ql : qh;
        cp_async16(base + (T_Q + arr * ATL + rr * RS + d8 * 8) * 2,
                   &src[(rowbase + qt * 128 + rr) * DD + colq + d8 * 8]);
    }
    #pragma unroll
    for (int it = 0; it < 16; it++) {
        int u = tid + it * 256;
        int arr = u >> 10, rem = u & 1023;
        int rr = rem >> 3, d8 = rem & 7;
        const ushortt* src = (arr == 0) ? kh : (arr == 1) ? kl : (arr == 2) ? vh : vl;
        cp_async16(base + (T_KV + arr * ATL + rr * RS + d8 * 8) * 2,
                   &src[(rowbase + 0 * 128 + rr) * DD + colq + d8 * 8]);
    }
    CP_COMMIT();

    float oacc[8][4];
    #pragma unroll
    for (int d = 0; d < 8; d++)
        #pragma unroll
        for (int e = 0; e < 4; e++) oacc[d][e] = 0.f;
    float mA = -INFINITY, mB = -INFINITY, lA = 0.f, lB = 0.f;

    int a_row = ((grp & 1) ? 8 : 0) + lr;
    int a_cof = (grp & 2) ? 8 : 0;
    int b_row = ((grp & 2) ? 8 : 0) + lr;
    int b_cof = (grp & 1) ? 8 : 0;
    int v_row = ((grp & 1) ? 8 : 0) + lr;
    int v_cof = (grp & 2) ? 8 : 0;

    for (int kt = 0; kt <= qt; kt++) {
        int buf = kt & 1;
        CP_WAIT0();
        __syncthreads();

        if (kt < qt) {   // prefetch tile kt+1 into other buffer
            #pragma unroll
            for (int it = 0; it < 16; it++) {
                int u = tid + it * 256;
                int arr = u >> 10, rem = u & 1023;
                int rr = rem >> 3, d8 = rem & 7;
                const ushortt* src = (arr == 0) ? kh : (arr == 1) ? kl : (arr == 2) ? vh : vl;
                cp_async16(base + (T_KV + (buf ^ 1) * KVBLK + arr * ATL + rr * RS + d8 * 8) * 2,
                           &src[(rowbase + (size_t)(kt + 1) * 128 + rr) * DD + colq + d8 * 8]);
            }
            CP_COMMIT();
        }

        uint32_t kvBase = base + (T_KV + buf * KVBLK) * 2;

        float sacc[16][4];
        #pragma unroll
        for (int nb = 0; nb < 16; nb++)
            #pragma unroll
            for (int e = 0; e < 4; e++) sacc[nb][e] = 0.f;

        #pragma unroll
        for (int kc = 0; kc < 4; kc++) {
            uint32_t Ah[4], Al[4];
            uint32_t qoff = ((m0 + a_row) * RS + kc * 16 + a_cof) * 2;
            ldmx4(Ah, base + T_Q * 2 + qoff);
            ldmx4(Al, base + (T_Q + ATL) * 2 + qoff);
            #pragma unroll
            for (int np = 0; np < 8; np++) {
                uint32_t Bh[4], Bl[4];
                uint32_t koff = ((np * 16 + b_row) * RS + kc * 16 + b_cof) * 2;
                ldmx4(Bh, kvBase + koff);                 // KH
                ldmx4(Bl, kvBase + ATL * 2 + koff);       // KL
                mma_bf16(sacc[2 * np],     Ah, Bh);
                mma_bf16(sacc[2 * np + 1], Ah, Bh + 2);
                mma_bf16(sacc[2 * np],     Ah, Bl);
                mma_bf16(sacc[2 * np + 1], Ah, Bl + 2);
                mma_bf16(sacc[2 * np],     Al, Bh);
                mma_bf16(sacc[2 * np + 1], Al, Bh + 2);
            }
        }

        // scale by 1/TEMP (exact power of two)
        #pragma unroll
        for (int nb = 0; nb < 16; nb++)
            #pragma unroll
            for (int e = 0; e < 4; e++) sacc[nb][e] *= 0.125f;

        int rAl = m0 + (lane >> 2);
        int cb = (lane & 3) * 2;
        if (kt == qt) {
            #pragma unroll
            for (int nb = 0; nb < 16; nb++) {
                int colL = nb * 8 + cb;
                if (colL     > rAl)     sacc[nb][0] = -INFINITY;
                if (colL + 1 > rAl)     sacc[nb][1] = -INFINITY;
                if (colL     > rAl + 8) sacc[nb][2] = -INFINITY;
                if (colL + 1 > rAl + 8) sacc[nb][3] = -INFINITY;
            }
        }
        float mxA = -INFINITY, mxB = -INFINITY;
        #pragma unroll
        for (int nb = 0; nb < 16; nb++) {
            mxA = fmaxf(mxA, fmaxf(sacc[nb][0], sacc[nb][1]));
            mxB = fmaxf(mxB, fmaxf(sacc[nb][2], sacc[nb][3]));
        }
        mxA = fmaxf(mxA, __shfl_xor_sync(0xffffffffu, mxA, 1));
        mxA = fmaxf(mxA, __shfl_xor_sync(0xffffffffu, mxA, 2));
        mxB = fmaxf(mxB, __shfl_xor_sync(0xffffffffu, mxB, 1));
        mxB = fmaxf(mxB, __shfl_xor_sync(0xffffffffu, mxB, 2));
        float mnA = fmaxf(mA, mxA), mnB = fmaxf(mB, mxB);
        float alA = __expf(mA - mnA), alB = __expf(mB - mnB);
        mA = mnA; mB = mnB;

        float lsA = 0.f, lsB = 0.f;
        #pragma unroll
        for (int nb = 0; nb < 16; nb++) {
            sacc[nb][0] = __expf(sacc[nb][0] - mnA); lsA += sacc[nb][0];
            sacc[nb][1] = __expf(sacc[nb][1] - mnA); lsA += sacc[nb][1];
            sacc[nb][2] = __expf(sacc[nb][2] - mnB); lsB += sacc[nb][2];
            sacc[nb][3] = __expf(sacc[nb][3] - mnB); lsB += sacc[nb][3];
        }
        lsA += __shfl_xor_sync(0xffffffffu, lsA, 1);
        lsA += __shfl_xor_sync(0xffffffffu, lsA, 2);
        lsB += __shfl_xor_sync(0xffffffffu, lsB, 1);
        lsB += __shfl_xor_sync(0xffffffffu, lsB, 2);
        lA = lA * alA + lsA;
        lB = lB * alB + lsB;
        #pragma unroll
        for (int d = 0; d < 8; d++) {
            oacc[d][0] *= alA; oacc[d][1] *= alA;
            oacc[d][2] *= alB; oacc[d][3] *= alB;
        }

        uint32_t ph[8][4], pl[8][4];
        #pragma unroll
        for (int jc = 0; jc < 8; jc++) {
            split2(sacc[2 * jc][0],     sacc[2 * jc][1],     ph[jc][0], pl[jc][0]);
            split2(sacc[2 * jc][2],     sacc[2 * jc][3],     ph[jc][1], pl[jc][1]);
            split2(sacc[2 * jc + 1][0], sacc[2 * jc + 1][1], ph[jc][2], pl[jc][2]);
            split2(sacc[2 * jc + 1][2], sacc[2 * jc + 1][3], ph[jc][3], pl[jc][3]);
        }

        #pragma unroll
        for (int jc = 0; jc < 8; jc++) {
            #pragma unroll
            for (int dp = 0; dp < 4; dp++) {
                uint32_t Bvh[4], Bvl[4];
                uint32_t voff = ((jc * 16 + v_row) * RS + dp * 16 + v_cof) * 2;
                ldmx4t(Bvh, kvBase + 2 * ATL * 2 + voff);   // VH
                ldmx4t(Bvl, kvBase + 3 * ATL * 2 + voff);   // VL
                mma_bf16(oacc[2 * dp],     ph[jc], Bvh);
                mma_bf16(oacc[2 * dp + 1], ph[jc], Bvh + 2);
                mma_bf16(oacc[2 * dp],     ph[jc], Bvl);
                mma_bf16(oacc[2 * dp + 1], ph[jc], Bvl + 2);
                mma_bf16(oacc[2 * dp],     pl[jc], Bvh);
                mma_bf16(oacc[2 * dp + 1], pl[jc], Bvh + 2);
            }
        }
    }

    float invA = 1.f / lA, invB = 1.f / lB;
    float* obase = att + (size_t)b * SS * DD + h * HD;
    int rgA = qt * 128 + m0 + (lane >> 2);
    int cb = (lane & 3) * 2;
    #pragma unroll
    for (int d = 0; d < 8; d++) {
        int col = d * 8 + cb;
        *(float2*)&obase[(size_t)rgA * DD + col] =
            make_float2(oacc[d][0] * invA, oacc[d][1] * invA);
        *(float2*)&obase[(size_t)(rgA + 8) * DD + col] =
            make_float2(oacc[d][2] * invB, oacc[d][3] * invB);
    }
}

extern "C" void kernel_launch(void* const* d_in, const int* in_sizes, int n_in,
                              void* d_out, int out_size) {
    const float* x   = (const float*)d_in[0];
    const float* Wq  = (const float*)d_in[1];
    const float* Wk  = (const float*)d_in[2];
    const float* Wv  = (const float*)d_in[3];
    const float* g1  = (const float*)d_in[4];
    const float* b1  = (const float*)d_in[5];
    const float* g2  = (const float*)d_in[6];
    const float* b2  = (const float*)d_in[7];
    const float* W1  = (const float*)d_in[8];
    const float* bf1 = (const float*)d_in[9];
    const float* W2  = (const float*)d_in[10];
    const float* bf2 = (const float*)d_in[11];
    float* out = (float*)d_out;

    ushortt *xnh, *xnl, *qh, *ql, *kh, *kl, *vh, *vl, *hh, *hl, *a1h, *a1l;
    float *att, *xt;
    cudaGetSymbolAddress((void**)&xnh, g_xnh); cudaGetSymbolAddress((void**)&xnl, g_xnl);
    cudaGetSymbolAddress((void**)&qh,  g_qh);  cudaGetSymbolAddress((void**)&ql,  g_ql);
    cudaGetSymbolAddress((void**)&kh,  g_kh);  cudaGetSymbolAddress((void**)&kl,  g_kl);
    cudaGetSymbolAddress((void**)&vh,  g_vh);  cudaGetSymbolAddress((void**)&vl,  g_vl);
    cudaGetSymbolAddress((void**)&hh,  g_hh);  cudaGetSymbolAddress((void**)&hl,  g_hl);
    cudaGetSymbolAddress((void**)&a1h, g_a1h); cudaGetSymbolAddress((void**)&a1l, g_a1l);
    cudaGetSymbolAddress((void**)&att, g_att); cudaGetSymbolAddress((void**)&xt,  g_xt);

    cudaFuncSetAttribute(attn_kernel, cudaFuncAttributeMaxDynamicSharedMemorySize, SMEM_ATTN);
    cudaFuncSetAttribute(gemm_tc, cudaFuncAttributeMaxDynamicSharedMemorySize, SMEM_GEMM);

    dim3 ggrid(DD / 128, NN / 128);   // (2, 128)

    // 1. xn = LN(x) -> bf16 hi/lo
    ln_split<<<NN, 256>>>(x, nullptr, g1, b1, nullptr, xnh, xnl);
    // 2. QKV projections -> bf16 hi/lo outputs
    gemm_tc<<<ggrid, 256, SMEM_GEMM>>>(xnh, xnl, Wq, nullptr, nullptr, nullptr, qh, ql, 0);
    gemm_tc<<<ggrid, 256, SMEM_GEMM>>>(xnh, xnl, Wk, nullptr, nullptr, nullptr, kh, kl, 0);
    gemm_tc<<<ggrid, 256, SMEM_GEMM>>>(xnh, xnl, Wv, nullptr, nullptr, nullptr, vh, vl, 0);
    // 3. causal flash attention (pre-split inputs)
    attn_kernel<<<dim3(SS / 128, BB * HH), 256, SMEM_ATTN>>>(qh, ql, kh, kl, vh, vl, att);
    // 4. xt = x + att; h = LN(xt) -> bf16 hi/lo
    ln_split<<<NN, 256>>>(x, att, g2, b2, xt, hh, hl);
    // 5. a1 = relu(h @ W1^T + bf1) -> bf16 hi/lo
    gemm_tc<<<ggrid, 256, SMEM_GEMM>>>(hh, hl, W1, bf1, nullptr, nullptr, a1h, a1l, 1);
    // 6. out = xt + a1 @ W2^T + bf2 (fp32)
    gemm_tc<<<ggrid, 256, SMEM_GEMM>>>(a1h, a1l, W2, bf2, xt, out, nullptr, nullptr, 2);
}

// round 14
// speedup vs baseline: 1.0101x; 1.0101x over previous
#include <cuda_runtime.h>
#include <cuda_bf16.h>
#include <math.h>
#include <stdint.h>

#define BB 4
#define SS 4096
#define DD 256
#define HH 4
#define HD 64
#define NN (BB*SS)
#define LN_EPS 1e-5f

typedef unsigned long long ull;

// Scratch (allocation-free): 8 x 16 MiB device globals.
__device__ float g_xn[NN*DD];
__device__ float g_q[NN*DD];
__device__ float g_k[NN*DD];
__device__ float g_v[NN*DD];
__device__ float g_att[NN*DD];
__device__ float g_xt[NN*DD];
__device__ float g_h[NN*DD];
__device__ float g_a1[NN*DD];

__device__ __forceinline__ uint32_t smem_u32(const void* p) {
    uint32_t a;
    asm("{ .reg .u64 t; cvta.to.shared.u64 t, %1; cvt.u32.u64 %0, t; }" : "=r"(a) : "l"(p));
    return a;
}

// ---- mma.sync / ldmatrix (base sm_80 ISA, valid on compute_103) ----
__device__ __forceinline__ void ldmx4(uint32_t* r, uint32_t a) {
    asm volatile("ldmatrix.sync.aligned.m8n8.x4.shared.b16 {%0,%1,%2,%3}, [%4];"
        : "=r"(r[0]), "=r"(r[1]), "=r"(r[2]), "=r"(r[3]) : "r"(a));
}
__device__ __forceinline__ void ldmx4t(uint32_t* r, uint32_t a) {
    asm volatile("ldmatrix.sync.aligned.m8n8.x4.trans.shared.b16 {%0,%1,%2,%3}, [%4];"
        : "=r"(r[0]), "=r"(r[1]), "=r"(r[2]), "=r"(r[3]) : "r"(a));
}
__device__ __forceinline__ void mma_bf16(float* c, const uint32_t* a, const uint32_t* b) {
    asm volatile("mma.sync.aligned.m16n8k16.row.col.f32.bf16.bf16.f32 "
        "{%0,%1,%2,%3}, {%4,%5,%6,%7}, {%8,%9}, {%0,%1,%2,%3};"
        : "+f"(c[0]), "+f"(c[1]), "+f"(c[2]), "+f"(c[3])
        : "r"(a[0]), "r"(a[1]), "r"(a[2]), "r"(a[3]), "r"(b[0]), "r"(b[1]));
}

// hi/lo bf16 split of an fp32 pair (packed bf16x2: e0 in low half).
__device__ __forceinline__ void split2(float e0, float e1, uint32_t& h, uint32_t& l) {
    __nv_bfloat162 hb = __floats2bfloat162_rn(e0, e1);
    h = reinterpret_cast<uint32_t&>(hb);
    float f0 = __bfloat162float(hb.x);
    float f1 = __bfloat162float(hb.y);
    __nv_bfloat162 lb = __floats2bfloat162_rn(e0 - f0, e1 - f1);
    l = reinterpret_cast<uint32_t&>(lb);
}

__device__ __forceinline__ float warp_sum(float v) {
    #pragma unroll
    for (int o = 16; o; o >>= 1) v += __shfl_xor_sync(0xffffffffu, v, o);
    return v;
}

// LayerNorm (optionally fused residual add). One block per row, 256 threads.
__global__ void ln_kernel(const float* __restrict__ x, const float* __restrict__ res,
                          const float* __restrict__ g, const float* __restrict__ b,
                          float* __restrict__ xt_out, float* __restrict__ y) {
    int row = blockIdx.x;
    int t = threadIdx.x;
    size_t i = (size_t)row * DD + t;
    float v = x[i];
    if (res) v += res[i];
    if (xt_out) xt_out[i] = v;

    __shared__ float red1[8], red2[8];
    float s1 = warp_sum(v);
    float s2 = warp_sum(v * v);
    if ((t & 31) == 0) { red1[t >> 5] = s1; red2[t >> 5] = s2; }
    __syncthreads();
    float tot = 0.f, tot2 = 0.f;
    #pragma unroll
    for (int w = 0; w < 8; w++) { tot += red1[w]; tot2 += red2[w]; }
    float mu = tot * (1.f / DD);
    float var = tot2 * (1.f / DD) - mu * mu;
    float rstd = rsqrtf(var + LN_EPS);
    y[i] = (v - mu) * rstd * g[t] + b[t];
}

// ---------------------------------------------------------------------------
// NT GEMM via mma.sync bf16 hi/lo (R12 base + B-fragment double buffering).
// CTA tile 128x128, K staged in 64-wide chunks as bf16 hi/lo (smem 72KB).
// 8 warps 4(M)x2(N), warp tile 32x64.
#define GRS 72
#define G_AH 0
#define G_AL (128*GRS)
#define G_BH (2*128*GRS)
#define G_BL (3*128*GRS)
#define SMEM_GEMM (4*128*GRS*2)   // 73728 B
__global__ void __launch_bounds__(256) gemm_tc(
        const float* __restrict__ A, const float* __restrict__ W,
        const float* __restrict__ bias, const float* __restrict__ res,
        float* __restrict__ C, int epi) {
    extern __shared__ unsigned short gsm[];
    uint32_t base = smem_u32(gsm);

    int tid = threadIdx.x;
    int w = tid >> 5, lane = tid & 31;
    int lr = lane & 7, grp = lane >> 3;
    int wm = w >> 1, wn = w & 1;
    int bm = blockIdx.y * 128, bn = blockIdx.x * 128;

    int a_row = ((grp & 1) ? 8 : 0) + lr;
    int a_cof = (grp & 2) ? 8 : 0;
    int b_row = ((grp & 2) ? 8 : 0) + lr;
    int b_cof = (grp & 1) ? 8 : 0;

    float cacc[2][8][4];
    #pragma unroll
    for (int am = 0; am < 2; am++)
        #pragma unroll
        for (int nb = 0; nb < 8; nb++)
            #pragma unroll
            for (int e = 0; e < 4; e++) cacc[am][nb][e] = 0.f;

    float4 pa[8], pw[8];
    #pragma unroll
    for (int it = 0; it < 8; it++) {
        int l = tid + it * 256;
        int rr = l >> 4, d4 = (l & 15) * 4;
        pa[it] = *(const float4*)&A[(size_t)(bm + rr) * DD + d4];
        pw[it] = *(const float4*)&W[(size_t)(bn + rr) * DD + d4];
    }

    for (int c = 0; c < 4; c++) {
        #pragma unroll
        for (int it = 0; it < 8; it++) {
            int l = tid + it * 256;
            int rr = l >> 4, d4 = (l & 15) * 4;
            uint32_t h01, l01, h23, l23;
            split2(pa[it].x, pa[it].y, h01, l01);
            split2(pa[it].z, pa[it].w, h23, l23);
            *(uint2*)&gsm[G_AH + rr * GRS + d4] = make_uint2(h01, h23);
            *(uint2*)&gsm[G_AL + rr * GRS + d4] = make_uint2(l01, l23);
            split2(pw[it].x, pw[it].y, h01, l01);
            split2(pw[it].z, pw[it].w, h23, l23);
            *(uint2*)&gsm[G_BH + rr * GRS + d4] = make_uint2(h01, h23);
            *(uint2*)&gsm[G_BL + rr * GRS + d4] = make_uint2(l01, l23);
        }
        __syncthreads();

        if (c < 3) {
            #pragma unroll
            for (int it = 0; it < 8; it++) {
                int l = tid + it * 256;
                int rr = l >> 4, d4 = (c + 1) * 64 + (l & 15) * 4;
                pa[it] = *(const float4*)&A[(size_t)(bm + rr) * DD + d4];
                pw[it] = *(const float4*)&W[(size_t)(bn + rr) * DD + d4];
            }
        }

        #pragma unroll
        for (int kc = 0; kc < 4; kc++) {
            uint32_t Ah[2][4], Al[2][4];
            #pragma unroll
            for (int am = 0; am < 2; am++) {
                uint32_t aoff = ((wm * 32 + am * 16 + a_row) * GRS + kc * 16 + a_cof) * 2;
                ldmx4(Ah[am], base + G_AH * 2 + aoff);
                ldmx4(Al[am], base + G_AL * 2 + aoff);
            }
            // B-fragment double buffer across np
            uint32_t Bh[2][4], Bl[2][4];
            {
                uint32_t boff = ((wn * 64 + b_row) * GRS + kc * 16 + b_cof) * 2;
                ldmx4(Bh[0], base + G_BH * 2 + boff);
                ldmx4(Bl[0], base + G_BL * 2 + boff);
            }
            #pragma unroll
            for (int np = 0; np < 4; np++) {
                int cur = np & 1;
                if (np < 3) {
                    uint32_t boff = ((wn * 64 + (np + 1) * 16 + b_row) * GRS + kc * 16 + b_cof) * 2;
                    ldmx4(Bh[cur ^ 1], base + G_BH * 2 + boff);
                    ldmx4(Bl[cur ^ 1], base + G_BL * 2 + boff);
                }
                #pragma unroll
                for (int am = 0; am < 2; am++) {
                    mma_bf16(cacc[am][2 * np],     Ah[am], Bh[cur]);
                    mma_bf16(cacc[am][2 * np + 1], Ah[am], Bh[cur] + 2);
                    mma_bf16(cacc[am][2 * np],     Ah[am], Bl[cur]);
                    mma_bf16(cacc[am][2 * np + 1], Ah[am], Bl[cur] + 2);
                    mma_bf16(cacc[am][2 * np],     Al[am], Bh[cur]);
                    mma_bf16(cacc[am][2 * np + 1], Al[am], Bh[cur] + 2);
                }
            }
        }
        __syncthreads();
    }

    int cb = (lane & 3) * 2;
    #pragma unroll
    for (int am = 0; am < 2; am++) {
        int r0 = bm + wm * 32 + am * 16 + (lane >> 2);
        #pragma unroll
        for (int nb = 0; nb < 8; nb++) {
            int col = bn + wn * 64 + nb * 8 + cb;
            #pragma unroll
            for (int half = 0; half < 2; half++) {
                int r = r0 + half * 8;
                float v0 = cacc[am][nb][2 * half];
                float v1 = cacc[am][nb][2 * half + 1];
                if (epi >= 1) { v0 += bias[col]; v1 += bias[col + 1]; }
                if (epi == 1) { v0 = fmaxf(v0, 0.f); v1 = fmaxf(v1, 0.f); }
                if (epi == 2) {
                    float2 rv = *(const float2*)&res[(size_t)r * DD + col];
                    v0 += rv.x; v1 += rv.y;
                }
                *(float2*)&C[(size_t)r * DD + col] = make_float2(v0, v1);
            }
        }
    }
}

// ---------------------------------------------------------------------------
// Flash attention via mma.sync bf16 hi/lo (R12 base + fragment double buffering
// in both S and PV phases).
#define RS 72
#define T_QH 0
#define T_QL (128*RS)
#define T_KH (2*128*RS)
#define T_KL (3*128*RS)
#define T_VH (4*128*RS)
#define T_VL (5*128*RS)
#define SMEM_ATTN (6*128*RS*2)   // 110592 B
__global__ void __launch_bounds__(256, 1) attn_kernel(
        const float* __restrict__ q, const float* __restrict__ k,
        const float* __restrict__ v, float* __restrict__ att) {
    extern __shared__ unsigned short sm16[];
    uint32_t base = smem_u32(sm16);

    int bh = blockIdx.y;
    int b = bh >> 2, h = bh & 3;
    int qt = 31 - blockIdx.x;           // longest first
    int tid = threadIdx.x;
    int w = tid >> 5, lane = tid & 31;
    int lr = lane & 7, grp = lane >> 3;
    int m0 = w * 16;

    const float* qbase = q + (size_t)b * SS * DD + h * HD;
    const float* kbase = k + (size_t)b * SS * DD + h * HD;
    const float* vbase = v + (size_t)b * SS * DD + h * HD;

    #pragma unroll
    for (int it = 0; it < 8; it++) {
        int l = tid + it * 256;
        int rr = l >> 4, d4 = (l & 15) * 4;
        float4 tv = *(const float4*)&qbase[(size_t)(qt * 128 + rr) * DD + d4];
        uint32_t h01, l01, h23, l23;
        split2(tv.x * 0.125f, tv.y * 0.125f, h01, l01);
        split2(tv.z * 0.125f, tv.w * 0.125f, h23, l23);
        *(uint2*)&sm16[T_QH + rr * RS + d4] = make_uint2(h01, h23);
        *(uint2*)&sm16[T_QL + rr * RS + d4] = make_uint2(l01, l23);
    }

    float oacc[8][4];
    #pragma unroll
    for (int d = 0; d < 8; d++)
        #pragma unroll
        for (int e = 0; e < 4; e++) oacc[d][e] = 0.f;
    float mA = -INFINITY, mB = -INFINITY, lA = 0.f, lB = 0.f;

    int a_row = ((grp & 1) ? 8 : 0) + lr;
    int a_cof = (grp & 2) ? 8 : 0;
    int b_row = ((grp & 2) ? 8 : 0) + lr;
    int b_cof = (grp & 1) ? 8 : 0;
    int v_row = ((grp & 1) ? 8 : 0) + lr;
    int v_cof = (grp & 2) ? 8 : 0;

    for (int kt = 0; kt <= qt; kt++) {
        #pragma unroll
        for (int it = 0; it < 8; it++) {
            int l = tid + it * 256;
            int rr = l >> 4, d4 = (l & 15) * 4;
            size_t gidx = (size_t)(kt * 128 + rr) * DD + d4;
            float4 kv = *(const float4*)&kbase[gidx];
            float4 vv = *(const float4*)&vbase[gidx];
            uint32_t h01, l01, h23, l23;
            split2(kv.x, kv.y, h01, l01); split2(kv.z, kv.w, h23, l23);
            *(uint2*)&sm16[T_KH + rr * RS + d4] = make_uint2(h01, h23);
            *(uint2*)&sm16[T_KL + rr * RS + d4] = make_uint2(l01, l23);
            split2(vv.x, vv.y, h01, l01); split2(vv.z, vv.w, h23, l23);
            *(uint2*)&sm16[T_VH + rr * RS + d4] = make_uint2(h01, h23);
            *(uint2*)&sm16[T_VL + rr * RS + d4] = make_uint2(l01, l23);
        }
        __syncthreads();

        // ---- S = Q @ K^T with K-fragment double buffering ----
        float sacc[16][4];
        #pragma unroll
        for (int nb = 0; nb < 16; nb++)
            #pragma unroll
            for (int e = 0; e < 4; e++) sacc[nb][e] = 0.f;

        #pragma unroll
        for (int kc = 0; kc < 4; kc++) {
            uint32_t Ah[4], Al[4];
            uint32_t qoff = ((m0 + a_row) * RS + kc * 16 + a_cof) * 2;
            ldmx4(Ah, base + T_QH * 2 + qoff);
            ldmx4(Al, base + T_QL * 2 + qoff);
            uint32_t Bh[2][4], Bl[2][4];
            {
                uint32_t koff = ((b_row) * RS + kc * 16 + b_cof) * 2;
                ldmx4(Bh[0], base + T_KH * 2 + koff);
                ldmx4(Bl[0], base + T_KL * 2 + koff);
            }
            #pragma unroll
            for (int np = 0; np < 8; np++) {
                int cur = np & 1;
                if (np < 7) {
                    uint32_t koff = (((np + 1) * 16 + b_row) * RS + kc * 16 + b_cof) * 2;
                    ldmx4(Bh[cur ^ 1], base + T_KH * 2 + koff);
                    ldmx4(Bl[cur ^ 1], base + T_KL * 2 + koff);
                }
                mma_bf16(sacc[2 * np],     Ah, Bh[cur]);
                mma_bf16(sacc[2 * np + 1], Ah, Bh[cur] + 2);
                mma_bf16(sacc[2 * np],     Ah, Bl[cur]);
                mma_bf16(sacc[2 * np + 1], Ah, Bl[cur] + 2);
                mma_bf16(sacc[2 * np],     Al, Bh[cur]);
                mma_bf16(sacc[2 * np + 1], Al, Bh[cur] + 2);
            }
        }

        int rAl = m0 + (lane >> 2);
        int cb = (lane & 3) * 2;
        if (kt == qt) {
            #pragma unroll
            for (int nb = 0; nb < 16; nb++) {
                int colL = nb * 8 + cb;
                if (colL     > rAl)     sacc[nb][0] = -INFINITY;
                if (colL + 1 > rAl)     sacc[nb][1] = -INFINITY;
                if (colL     > rAl + 8) sacc[nb][2] = -INFINITY;
                if (colL + 1 > rAl + 8) sacc[nb][3] = -INFINITY;
            }
        }
        float mxA = -INFINITY, mxB = -INFINITY;
        #pragma unroll
        for (int nb = 0; nb < 16; nb++) {
            mxA = fmaxf(mxA, fmaxf(sacc[nb][0], sacc[nb][1]));
            mxB = fmaxf(mxB, fmaxf(sacc[nb][2], sacc[nb][3]));
        }
        mxA = fmaxf(mxA, __shfl_xor_sync(0xffffffffu, mxA, 1));
        mxA = fmaxf(mxA, __shfl_xor_sync(0xffffffffu, mxA, 2));
        mxB = fmaxf(mxB, __shfl_xor_sync(0xffffffffu, mxB, 1));
        mxB = fmaxf(mxB, __shfl_xor_sync(0xffffffffu, mxB, 2));
        float mnA = fmaxf(mA, mxA), mnB = fmaxf(mB, mxB);
        float alA = __expf(mA - mnA), alB = __expf(mB - mnB);
        mA = mnA; mB = mnB;

        float lsA = 0.f, lsB = 0.f;
        #pragma unroll
        for (int nb = 0; nb < 16; nb++) {
            sacc[nb][0] = __expf(sacc[nb][0] - mnA); lsA += sacc[nb][0];
            sacc[nb][1] = __expf(sacc[nb][1] - mnA); lsA += sacc[nb][1];
            sacc[nb][2] = __expf(sacc[nb][2] - mnB); lsB += sacc[nb][2];
            sacc[nb][3] = __expf(sacc[nb][3] - mnB); lsB += sacc[nb][3];
        }
        lsA += __shfl_xor_sync(0xffffffffu, lsA, 1);
        lsA += __shfl_xor_sync(0xffffffffu, lsA, 2);
        lsB += __shfl_xor_sync(0xffffffffu, lsB, 1);
        lsB += __shfl_xor_sync(0xffffffffu, lsB, 2);
        lA = lA * alA + lsA;
        lB = lB * alB + lsB;
        #pragma unroll
        for (int d = 0; d < 8; d++) {
            oacc[d][0] *= alA; oacc[d][1] *= alA;
            oacc[d][2] *= alB; oacc[d][3] *= alB;
        }

        uint32_t ph[8][4], pl[8][4];
        #pragma unroll
        for (int jc = 0; jc < 8; jc++) {
            split2(sacc[2 * jc][0],     sacc[2 * jc][1],     ph[jc][0], pl[jc][0]);
            split2(sacc[2 * jc][2],     sacc[2 * jc][3],     ph[jc][1], pl[jc][1]);
            split2(sacc[2 * jc + 1][0], sacc[2 * jc + 1][1], ph[jc][2], pl[jc][2]);
            split2(sacc[2 * jc + 1][2], sacc[2 * jc + 1][3], ph[jc][3], pl[jc][3]);
        }

        // ---- O += P @ V with V-fragment double buffering ----
        uint32_t Vh[2][4], Vl[2][4];
        {
            uint32_t voff = ((v_row) * RS + v_cof) * 2;
            ldmx4t(Vh[0], base + T_VH * 2 + voff);
            ldmx4t(Vl[0], base + T_VL * 2 + voff);
        }
        #pragma unroll
        for (int jc = 0; jc < 8; jc++) {
            #pragma unroll
            for (int dp = 0; dp < 4; dp++) {
                int idx = jc * 4 + dp;
                int cur = idx & 1;
                if (idx < 31) {
                    int nj = (idx + 1) >> 2, nd = (idx + 1) & 3;
                    uint32_t voff = ((nj * 16 + v_row) * RS + nd * 16 + v_cof) * 2;
                    ldmx4t(Vh[cur ^ 1], base + T_VH * 2 + voff);
                    ldmx4t(Vl[cur ^ 1], base + T_VL * 2 + voff);
                }
                mma_bf16(oacc[2 * dp],     ph[jc], Vh[cur]);
                mma_bf16(oacc[2 * dp + 1], ph[jc], Vh[cur] + 2);
                mma_bf16(oacc[2 * dp],     ph[jc], Vl[cur]);
                mma_bf16(oacc[2 * dp + 1], ph[jc], Vl[cur] + 2);
                mma_bf16(oacc[2 * dp],     pl[jc], Vh[cur]);
                mma_bf16(oacc[2 * dp + 1], pl[jc], Vh[cur] + 2);
            }
        }
        __syncthreads();
    }

    float invA = 1.f / lA, invB = 1.f / lB;
    float* obase = att + (size_t)b * SS * DD + h * HD;
    int rgA = qt * 128 + m0 + (lane >> 2);
    int cb = (lane & 3) * 2;
    #pragma unroll
    for (int d = 0; d < 8; d++) {
        int col = d * 8 + cb;
        *(float2*)&obase[(size_t)rgA * DD + col] =
            make_float2(oacc[d][0] * invA, oacc[d][1] * invA);
        *(float2*)&obase[(size_t)(rgA + 8) * DD + col] =
            make_float2(oacc[d][2] * invB, oacc[d][3] * invB);
    }
}

extern "C" void kernel_launch(void* const* d_in, const int* in_sizes, int n_in,
                              void* d_out, int out_size) {
    const float* x   = (const float*)d_in[0];
    const float* Wq  = (const float*)d_in[1];
    const float* Wk  = (const float*)d_in[2];
    const float* Wv  = (const float*)d_in[3];
    const float* g1  = (const float*)d_in[4];
    const float* b1  = (const float*)d_in[5];
    const float* g2  = (const float*)d_in[6];
    const float* b2  = (const float*)d_in[7];
    const float* W1  = (const float*)d_in[8];
    const float* bf1 = (const float*)d_in[9];
    const float* W2  = (const float*)d_in[10];
    const float* bf2 = (const float*)d_in[11];
    float* out = (float*)d_out;

    float *xn, *q, *k, *v, *att, *xt, *h, *a1;
    cudaGetSymbolAddress((void**)&xn,  g_xn);
    cudaGetSymbolAddress((void**)&q,   g_q);
    cudaGetSymbolAddress((void**)&k,   g_k);
    cudaGetSymbolAddress((void**)&v,   g_v);
    cudaGetSymbolAddress((void**)&att, g_att);
    cudaGetSymbolAddress((void**)&xt,  g_xt);
    cudaGetSymbolAddress((void**)&h,   g_h);
    cudaGetSymbolAddress((void**)&a1,  g_a1);

    cudaFuncSetAttribute(attn_kernel, cudaFuncAttributeMaxDynamicSharedMemorySize, SMEM_ATTN);
    cudaFuncSetAttribute(gemm_tc, cudaFuncAttributeMaxDynamicSharedMemorySize, SMEM_GEMM);

    dim3 ggrid(DD / 128, NN / 128);   // (2, 128)

    // 1. xn = LN(x)
    ln_kernel<<<NN, 256>>>(x, nullptr, g1, b1, nullptr, xn);
    // 2. QKV projections (mma.sync bf16 hi/lo)
    gemm_tc<<<ggrid, 256, SMEM_GEMM>>>(xn, Wq, nullptr, nullptr, q, 0);
    gemm_tc<<<ggrid, 256, SMEM_GEMM>>>(xn, Wk, nullptr, nullptr, k, 0);
    gemm_tc<<<ggrid, 256, SMEM_GEMM>>>(xn, Wv, nullptr, nullptr, v, 0);
    // 3. causal flash attention (mma.sync bf16 hi/lo)
    attn_kernel<<<dim3(SS / 128, BB * HH), 256, SMEM_ATTN>>>(q, k, v, att);
    // 4. xt = x + att; h = LN(xt)
    ln_kernel<<<NN, 256>>>(x, att, g2, b2, xt, h);
    // 5. a1 = relu(h @ W1^T + bf1)
    gemm_tc<<<ggrid, 256, SMEM_GEMM>>>(h, W1, bf1, nullptr, a1, 1);
    // 6. out = xt + a1 @ W2^T + bf2
    gemm_tc<<<ggrid, 256, SMEM_GEMM>>>(a1, W2, bf2, xt, out, 2);
}